// round 9
// baseline (speedup 1.0000x reference)
#include <cuda_runtime.h>
#include <math.h>

#define B_ROWS 65536
#define C_CLS  1000
#define C4     250        // 1000 floats = 250 float4 per row
#define BETA_F 3.0f
#define LOG2E_F 1.4426950408889634f
#define EPI_BLOCKS 512
#define DOT_BLOCKS 256

// ---- scratch (no allocations allowed; zero-initialized at module load) ----
__device__ __align__(16) int    g_counts[C_CLS * C_CLS];
__device__ __align__(16) float  g_cmn[C_CLS * C_CLS];   // (cost+counts)*scale
__device__ __align__(16) float2 g_pair[B_ROWS];         // {glp, bits(t*1000+p)}
__device__ float  g_partial[DOT_BLOCKS];
__device__ unsigned int g_sync1;   // phase-1 arrivals (reset by last dot block)
__device__ unsigned int g_sync2;   // dot-block arrivals (reset by last dot block)

// ---------------------------------------------------------------------------
// k1: one warp per row, TWO passes. Pass 1: FMNMX-only row max (fills L1).
// Pass 2: re-read row from L1 -> sumexp + argmax-by-equality (min index of
// v==m, exact bits, = first-index jnp.argmax). No 32-reg value array ->
// occupancy up. 262 MB streamed once from DRAM, second read is L1-resident
// (6 blocks * 32KB = 192KB <= 228KB L1).
// ---------------------------------------------------------------------------
__global__ __launch_bounds__(256, 6) void k_rows(
    const float* __restrict__ outp, const void* __restrict__ tgt)
{
    int tid  = threadIdx.x;
    int lane = tid & 31;
    int warp = (blockIdx.x * 256 + tid) >> 5;

    // Per-warp dtype detect (no sync): int64 targets in [0,1000) have all-zero
    // odd 32-bit words. Scan odd words of the first 64 entries.
    const int* tw = (const int*)tgt;
    int nz = tw[4 * lane + 1] | tw[4 * lane + 3];
    int is64 = (__ballot_sync(0xffffffffu, nz != 0) == 0u);

    const float*  row = outp + (size_t)warp * C_CLS;
    const float4* rp  = (const float4*)row;

    // Prefetch target index + target logit on lane 0 (overlaps row loads).
    int   t  = 0;
    float xt = 0.0f;
    if (lane == 0) {
        t  = is64 ? (int)((const long long*)tgt)[warp]
                  : ((const int*)tgt)[warp];
        xt = row[t];
    }

    // Pass 1: row max only (1 FMNMX per element).
    float m = -INFINITY;
    #pragma unroll
    for (int i = 0; i < 8; i++) {
        int idx4 = lane + i * 32;
        if (idx4 < C4) {
            float4 v = rp[idx4];
            m = fmaxf(m, fmaxf(fmaxf(v.x, v.y), fmaxf(v.z, v.w)));
        }
    }
    #pragma unroll
    for (int off = 16; off; off >>= 1)
        m = fmaxf(m, __shfl_xor_sync(0xffffffffu, m, off));

    // Pass 2: reload from L1 (.cs: last use), sumexp + first index of max.
    float nml = -m * LOG2E_F;
    float s0 = 0.f, s1 = 0.f, s2 = 0.f, s3 = 0.f;
    int am = 0x7fffffff;
    #pragma unroll
    for (int i = 0; i < 8; i++) {
        int idx4 = lane + i * 32;
        if (idx4 < C4) {
            float4 v = __ldcs(rp + idx4);
            int base = idx4 * 4;
            s0 += exp2f(fmaf(v.x, LOG2E_F, nml));
            s1 += exp2f(fmaf(v.y, LOG2E_F, nml));
            s2 += exp2f(fmaf(v.z, LOG2E_F, nml));
            s3 += exp2f(fmaf(v.w, LOG2E_F, nml));
            if (v.x == m) am = min(am, base + 0);
            if (v.y == m) am = min(am, base + 1);
            if (v.z == m) am = min(am, base + 2);
            if (v.w == m) am = min(am, base + 3);
        }
    }
    float s = (s0 + s1) + (s2 + s3);
    #pragma unroll
    for (int off = 16; off; off >>= 1) {
        s  += __shfl_xor_sync(0xffffffffu, s, off);
        am  = min(am, __shfl_xor_sync(0xffffffffu, am, off));
    }

    if (lane == 0) {
        float glp = xt - m - __logf(s);
        int idx = t * C_CLS + am;
        g_pair[warp] = make_float2(glp, __int_as_float(idx));
        atomicAdd(&g_counts[idx], 1);
    }
}

// ---------------------------------------------------------------------------
// k2 (fused epilogue): 512 blocks, all guaranteed co-resident (256 thr,
// <=64 regs -> >=4 blocks/SM -> 592 slots >= 512).
//  Phase 1: each block normalizes class rows bid and bid+512:
//           cmn = (cost+counts)*beta/max(1,rowsum); zeroes its counts rows.
//  Grid barrier (fence + counter spin).
//  Phase 2: blocks 0..255 gather-dot the 64K samples, tree-reduce to
//           partials; fenced last block does the final deterministic sum,
//           writes -mean, resets both counters for graph replay.
// ---------------------------------------------------------------------------
__global__ __launch_bounds__(256) void k_epi(
    const float* __restrict__ cost, float* __restrict__ out)
{
    int bid = blockIdx.x, tid = threadIdx.x;
    __shared__ float sh[256];

    // ---- phase 1: row normalization ----
    #pragma unroll
    for (int rr = 0; rr < 2; rr++) {
        int r = bid + rr * EPI_BLOCKS;
        if (r < C_CLS) {                      // uniform per block
            float4 res = make_float4(0.f, 0.f, 0.f, 0.f);
            float  s   = 0.0f;
            if (tid < C4) {
                float4 cv = *(const float4*)(cost + (size_t)r * C_CLS + tid * 4);
                int4   nv = *(const int4*)(g_counts + (size_t)r * C_CLS + tid * 4);
                res.x = cv.x + (float)nv.x;
                res.y = cv.y + (float)nv.y;
                res.z = cv.z + (float)nv.z;
                res.w = cv.w + (float)nv.w;
                s = (res.x + res.y) + (res.z + res.w);
            }
            sh[tid] = s;
            __syncthreads();
            #pragma unroll
            for (int off = 128; off; off >>= 1) {
                if (tid < off) sh[tid] += sh[tid + off];
                __syncthreads();
            }
            float scale = BETA_F / fmaxf(1.0f, sh[0]);
            if (tid < C4) {
                *(float4*)(g_cmn + (size_t)r * C_CLS + tid * 4) =
                    make_float4(res.x * scale, res.y * scale,
                                res.z * scale, res.w * scale);
                *(int4*)(g_counts + (size_t)r * C_CLS + tid * 4) =
                    make_int4(0, 0, 0, 0);
            }
            __syncthreads();
        }
    }

    // ---- grid barrier ----
    __threadfence();
    __syncthreads();
    if (tid == 0) atomicAdd(&g_sync1, 1u);

    if (bid >= DOT_BLOCKS) return;

    if (tid == 0) {
        while (atomicAdd(&g_sync1, 0u) < (unsigned)EPI_BLOCKS) { }
    }
    __syncthreads();

    // ---- phase 2: gather-dot ----
    int b = bid * 256 + tid;                  // exactly B_ROWS threads
    float2 pr = g_pair[b];
    float acc = pr.x * __ldcg(&g_cmn[__float_as_int(pr.y)]);

    #pragma unroll
    for (int off = 16; off; off >>= 1)
        acc += __shfl_xor_sync(0xffffffffu, acc, off);

    __shared__ float shw[8];
    __shared__ bool  is_last;
    if ((tid & 31) == 0) shw[tid >> 5] = acc;
    __syncthreads();
    if (tid == 0) {
        float sB = ((shw[0] + shw[1]) + (shw[2] + shw[3]))
                 + ((shw[4] + shw[5]) + (shw[6] + shw[7]));
        g_partial[bid] = sB;
        __threadfence();
        unsigned done = atomicAdd(&g_sync2, 1u);
        is_last = (done == (unsigned)(DOT_BLOCKS - 1));
    }
    __syncthreads();

    if (is_last) {
        sh[tid] = g_partial[tid];
        __syncthreads();
        #pragma unroll
        for (int off = DOT_BLOCKS / 2; off; off >>= 1) {
            if (tid < off) sh[tid] += sh[tid + off];
            __syncthreads();
        }
        if (tid == 0) {
            out[0]  = -sh[0] / (float)B_ROWS;
            g_sync1 = 0u;                     // ready for next graph replay
            g_sync2 = 0u;
        }
    }
}

extern "C" void kernel_launch(void* const* d_in, const int* in_sizes, int n_in,
                              void* d_out, int out_size) {
    const float* outputs = (const float*)d_in[0];
    const void*  targets = d_in[1];
    const float* cost    = (const float*)d_in[2];
    float* out = (float*)d_out;

    k_rows<<<B_ROWS / 8, 256>>>(outputs, targets);   // 8 warps/block
    k_epi <<<EPI_BLOCKS, 256>>>(cost, out);
}

// round 10
// speedup vs baseline: 1.0048x; 1.0048x over previous
#include <cuda_runtime.h>
#include <math.h>

#define B_ROWS 65536
#define C_CLS  1000
#define C4     250        // 1000 floats = 250 float4 per row
#define BETA_F 3.0f
#define LOG2E_F 1.4426950408889634f
#define DOT_BLOCKS 256
#define ROWS_BLOCKS 592   // 4 blocks/SM * 148 SMs -> single persistent wave
#define ROWS_WARPS (ROWS_BLOCKS * 8)

// ---- scratch (no allocations allowed; zero-initialized at module load) ----
__device__ __align__(16) int    g_counts[C_CLS * C_CLS];
__device__ __align__(16) float  g_cmn[C_CLS * C_CLS];   // (cost+counts)*scale
__device__ __align__(16) float2 g_pair[B_ROWS];         // {glp, bits(t*1000+p)}
__device__ float  g_partial[DOT_BLOCKS];
__device__ unsigned int g_done;                          // reset by k_dot last block

// ---------------------------------------------------------------------------
// k1: PERSISTENT one-warp-per-row, grid-stride over rows (single wave, no
// wave-transition stalls). Per row: two passes. Pass 1: FMNMX-only max
// (fills L1). Pass 2: L1 re-read (.cs, last use) -> sumexp + argmax-by-
// equality (min index of v==m, exact bits = first-index jnp.argmax).
// L1 budget: <=6 blocks * 8 warps * 4KB = 192KB <= 228KB.
// ---------------------------------------------------------------------------
__global__ __launch_bounds__(256, 6) void k_rows(
    const float* __restrict__ outp, const void* __restrict__ tgt)
{
    int tid   = threadIdx.x;
    int lane  = tid & 31;
    int gwarp = (blockIdx.x * 256 + tid) >> 5;

    // Per-warp dtype detect (hoisted): int64 targets in [0,1000) have
    // all-zero odd 32-bit words. Scan odd words of the first 64 entries.
    const int* tw = (const int*)tgt;
    int nz = tw[4 * lane + 1] | tw[4 * lane + 3];
    int is64 = (__ballot_sync(0xffffffffu, nz != 0) == 0u);
    const long long* t64 = (const long long*)tgt;
    const int*       t32 = (const int*)tgt;

    for (int row_i = gwarp; row_i < B_ROWS; row_i += ROWS_WARPS) {
        const float*  row = outp + (size_t)row_i * C_CLS;
        const float4* rp  = (const float4*)row;

        // Prefetch target index + target logit on lane 0 (overlaps loads).
        int   t  = 0;
        float xt = 0.0f;
        if (lane == 0) {
            t  = is64 ? (int)t64[row_i] : t32[row_i];
            xt = row[t];
        }

        // Pass 1: row max only (1 FMNMX per element).
        float m = -INFINITY;
        #pragma unroll
        for (int i = 0; i < 8; i++) {
            int idx4 = lane + i * 32;
            if (idx4 < C4) {
                float4 v = rp[idx4];
                m = fmaxf(m, fmaxf(fmaxf(v.x, v.y), fmaxf(v.z, v.w)));
            }
        }
        #pragma unroll
        for (int off = 16; off; off >>= 1)
            m = fmaxf(m, __shfl_xor_sync(0xffffffffu, m, off));

        // Pass 2: reload from L1 (.cs: last use), sumexp + first max index.
        float nml = -m * LOG2E_F;
        float s0 = 0.f, s1 = 0.f, s2 = 0.f, s3 = 0.f;
        int am = 0x7fffffff;
        #pragma unroll
        for (int i = 0; i < 8; i++) {
            int idx4 = lane + i * 32;
            if (idx4 < C4) {
                float4 v = __ldcs(rp + idx4);
                int base = idx4 * 4;
                s0 += exp2f(fmaf(v.x, LOG2E_F, nml));
                s1 += exp2f(fmaf(v.y, LOG2E_F, nml));
                s2 += exp2f(fmaf(v.z, LOG2E_F, nml));
                s3 += exp2f(fmaf(v.w, LOG2E_F, nml));
                if (v.x == m) am = min(am, base + 0);
                if (v.y == m) am = min(am, base + 1);
                if (v.z == m) am = min(am, base + 2);
                if (v.w == m) am = min(am, base + 3);
            }
        }
        float s = (s0 + s1) + (s2 + s3);
        #pragma unroll
        for (int off = 16; off; off >>= 1) {
            s  += __shfl_xor_sync(0xffffffffu, s, off);
            am  = min(am, __shfl_xor_sync(0xffffffffu, am, off));
        }

        if (lane == 0) {
            float glp = xt - m - __logf(s);
            int idx = t * C_CLS + am;
            g_pair[row_i] = make_float2(glp, __int_as_float(idx));
            atomicAdd(&g_counts[idx], 1);
        }
    }
}

// ---------------------------------------------------------------------------
// k2: one block per class row, one float4/int4 per thread (250 active).
// cmn = (cost+counts) * beta / max(1, rowsum); zeroes counts row for the
// next call (block-local -> race-free).
// ---------------------------------------------------------------------------
__global__ __launch_bounds__(256) void k_scale(const float* __restrict__ cost) {
    int r  = blockIdx.x;
    int c4 = threadIdx.x;
    float4 res = make_float4(0.f, 0.f, 0.f, 0.f);
    float  s   = 0.0f;
    if (c4 < C4) {
        float4 cv = *(const float4*)(cost + (size_t)r * C_CLS + c4 * 4);
        int4   nv = *(const int4*)(g_counts + (size_t)r * C_CLS + c4 * 4);
        res.x = cv.x + (float)nv.x;
        res.y = cv.y + (float)nv.y;
        res.z = cv.z + (float)nv.z;
        res.w = cv.w + (float)nv.w;
        s = (res.x + res.y) + (res.z + res.w);
    }
    __shared__ float sh[256];
    sh[threadIdx.x] = s;
    __syncthreads();
    #pragma unroll
    for (int off = 128; off; off >>= 1) {
        if (threadIdx.x < off) sh[threadIdx.x] += sh[threadIdx.x + off];
        __syncthreads();
    }
    float scale = BETA_F / fmaxf(1.0f, sh[0]);
    if (c4 < C4) {
        *(float4*)(g_cmn + (size_t)r * C_CLS + c4 * 4) =
            make_float4(res.x * scale, res.y * scale,
                        res.z * scale, res.w * scale);
        *(int4*)(g_counts + (size_t)r * C_CLS + c4 * 4) = make_int4(0, 0, 0, 0);
    }
}

// ---------------------------------------------------------------------------
// k3: per-sample gather + product (1 coalesced float2 + 1 L2 gather),
// warp-shuffle reduce -> partials; fenced last block finishes the
// deterministic tree sum, writes -mean, resets g_done for the next replay.
// ---------------------------------------------------------------------------
__global__ __launch_bounds__(256) void k_dot(float* __restrict__ out) {
    int b = blockIdx.x * 256 + threadIdx.x;
    float2 pr = g_pair[b];                       // exactly B_ROWS threads
    float acc = pr.x * g_cmn[__float_as_int(pr.y)];

    #pragma unroll
    for (int off = 16; off; off >>= 1)
        acc += __shfl_xor_sync(0xffffffffu, acc, off);

    __shared__ float shw[8];
    __shared__ bool  is_last;
    int wid = threadIdx.x >> 5;
    if ((threadIdx.x & 31) == 0) shw[wid] = acc;
    __syncthreads();
    if (threadIdx.x == 0) {
        float sB = ((shw[0] + shw[1]) + (shw[2] + shw[3]))
                 + ((shw[4] + shw[5]) + (shw[6] + shw[7]));
        g_partial[blockIdx.x] = sB;
        __threadfence();
        unsigned done = atomicAdd(&g_done, 1u);
        is_last = (done == (unsigned)(DOT_BLOCKS - 1));
    }
    __syncthreads();

    if (is_last) {
        __shared__ float sh[DOT_BLOCKS];
        sh[threadIdx.x] = g_partial[threadIdx.x];
        __syncthreads();
        #pragma unroll
        for (int off = DOT_BLOCKS / 2; off; off >>= 1) {
            if (threadIdx.x < off) sh[threadIdx.x] += sh[threadIdx.x + off];
            __syncthreads();
        }
        if (threadIdx.x == 0) {
            out[0] = -sh[0] / (float)B_ROWS;
            g_done = 0u;                          // ready for next replay
        }
    }
}

extern "C" void kernel_launch(void* const* d_in, const int* in_sizes, int n_in,
                              void* d_out, int out_size) {
    const float* outputs = (const float*)d_in[0];
    const void*  targets = d_in[1];
    const float* cost    = (const float*)d_in[2];
    float* out = (float*)d_out;

    k_rows <<<ROWS_BLOCKS, 256>>>(outputs, targets);  // persistent, 1 wave
    k_scale<<<C_CLS, 256>>>(cost);
    k_dot  <<<DOT_BLOCKS, 256>>>(out);
}

// round 11
// speedup vs baseline: 1.0454x; 1.0404x over previous
#include <cuda_runtime.h>
#include <math.h>

#define B_ROWS 65536
#define C_CLS  1000
#define C4     250        // 1000 floats = 250 float4 per row
#define BETA_F 3.0f
#define LOG2E_F 1.4426950408889634f
#define DOT_BLOCKS 256
#define ROWS_BLOCKS 888   // 6 blocks/SM * 148 SMs -> single wave, 75% occ cap
#define ROWS_WARPS (ROWS_BLOCKS * 8)

// ---- scratch (no allocations allowed; zero-initialized at module load) ----
__device__ __align__(16) int    g_counts[C_CLS * C_CLS];
__device__ __align__(16) float  g_cmn[C_CLS * C_CLS];   // (cost+counts)*scale
__device__ __align__(16) float2 g_pair[B_ROWS];         // {glp, bits(t*1000+p)}
__device__ float  g_partial[DOT_BLOCKS];
__device__ unsigned int g_done;                          // reset by k_dot last block

// ---------------------------------------------------------------------------
// k1: PERSISTENT one-warp-per-row, grid-stride (single wave), 6 blocks/SM.
// Per row: pass 1 = FMNMX-only max (fills L1); pass 2 = L1 re-read (.cs)
// -> sumexp + argmax-by-equality (min index of v==m, exact bits = first-index
// jnp.argmax). Quads 0..223 unconditional; tail quad predicated once.
// L1 budget: 6 blocks * 8 warps * 4KB = 192KB <= 228KB.
// ---------------------------------------------------------------------------
__global__ __launch_bounds__(256, 6) void k_rows(
    const float* __restrict__ outp, const void* __restrict__ tgt)
{
    int tid   = threadIdx.x;
    int lane  = tid & 31;
    int gwarp = (blockIdx.x * 256 + tid) >> 5;

    // Per-warp dtype detect (hoisted): int64 targets in [0,1000) have
    // all-zero odd 32-bit words. Scan odd words of the first 64 entries.
    const int* tw = (const int*)tgt;
    int nz = tw[4 * lane + 1] | tw[4 * lane + 3];
    int is64 = (__ballot_sync(0xffffffffu, nz != 0) == 0u);
    const long long* t64 = (const long long*)tgt;
    const int*       t32 = (const int*)tgt;

    bool tail = (lane < (C4 - 224));            // last quad valid?

    for (int row_i = gwarp; row_i < B_ROWS; row_i += ROWS_WARPS) {
        const float*  row = outp + (size_t)row_i * C_CLS;
        const float4* rp  = (const float4*)row;

        // Prefetch target index + target logit on lane 0 (overlaps loads).
        int   t  = 0;
        float xt = 0.0f;
        if (lane == 0) {
            t  = is64 ? (int)t64[row_i] : t32[row_i];
            xt = row[t];
        }

        // Pass 1: row max only (1 FMNMX per element), unconditional body.
        float m = -INFINITY;
        #pragma unroll
        for (int i = 0; i < 7; i++) {
            float4 v = rp[lane + i * 32];
            m = fmaxf(m, fmaxf(fmaxf(v.x, v.y), fmaxf(v.z, v.w)));
        }
        if (tail) {
            float4 v = rp[lane + 224];
            m = fmaxf(m, fmaxf(fmaxf(v.x, v.y), fmaxf(v.z, v.w)));
        }
        #pragma unroll
        for (int off = 16; off; off >>= 1)
            m = fmaxf(m, __shfl_xor_sync(0xffffffffu, m, off));

        // Pass 2: reload from L1 (.cs: last use), sumexp + first max index.
        float nml = -m * LOG2E_F;
        float s0 = 0.f, s1 = 0.f, s2 = 0.f, s3 = 0.f;
        int am = 0x7fffffff;
        #pragma unroll
        for (int i = 0; i < 7; i++) {
            int idx4 = lane + i * 32;
            float4 v = __ldcs(rp + idx4);
            int base = idx4 * 4;
            s0 += exp2f(fmaf(v.x, LOG2E_F, nml));
            s1 += exp2f(fmaf(v.y, LOG2E_F, nml));
            s2 += exp2f(fmaf(v.z, LOG2E_F, nml));
            s3 += exp2f(fmaf(v.w, LOG2E_F, nml));
            if (v.x == m) am = min(am, base + 0);
            if (v.y == m) am = min(am, base + 1);
            if (v.z == m) am = min(am, base + 2);
            if (v.w == m) am = min(am, base + 3);
        }
        if (tail) {
            int idx4 = lane + 224;
            float4 v = __ldcs(rp + idx4);
            int base = idx4 * 4;
            s0 += exp2f(fmaf(v.x, LOG2E_F, nml));
            s1 += exp2f(fmaf(v.y, LOG2E_F, nml));
            s2 += exp2f(fmaf(v.z, LOG2E_F, nml));
            s3 += exp2f(fmaf(v.w, LOG2E_F, nml));
            if (v.x == m) am = min(am, base + 0);
            if (v.y == m) am = min(am, base + 1);
            if (v.z == m) am = min(am, base + 2);
            if (v.w == m) am = min(am, base + 3);
        }
        float s = (s0 + s1) + (s2 + s3);
        #pragma unroll
        for (int off = 16; off; off >>= 1) {
            s  += __shfl_xor_sync(0xffffffffu, s, off);
            am  = min(am, __shfl_xor_sync(0xffffffffu, am, off));
        }

        if (lane == 0) {
            float glp = xt - m - __logf(s);
            int idx = t * C_CLS + am;
            g_pair[row_i] = make_float2(glp, __int_as_float(idx));
            atomicAdd(&g_counts[idx], 1);
        }
    }
}

// ---------------------------------------------------------------------------
// k2: one block per class row, one float4/int4 per thread (250 active).
// cmn = (cost+counts) * beta / max(1, rowsum); zeroes counts row for the
// next call (block-local -> race-free).
// ---------------------------------------------------------------------------
__global__ __launch_bounds__(256) void k_scale(const float* __restrict__ cost) {
    int r  = blockIdx.x;
    int c4 = threadIdx.x;
    float4 res = make_float4(0.f, 0.f, 0.f, 0.f);
    float  s   = 0.0f;
    if (c4 < C4) {
        float4 cv = *(const float4*)(cost + (size_t)r * C_CLS + c4 * 4);
        int4   nv = *(const int4*)(g_counts + (size_t)r * C_CLS + c4 * 4);
        res.x = cv.x + (float)nv.x;
        res.y = cv.y + (float)nv.y;
        res.z = cv.z + (float)nv.z;
        res.w = cv.w + (float)nv.w;
        s = (res.x + res.y) + (res.z + res.w);
    }
    __shared__ float sh[256];
    sh[threadIdx.x] = s;
    __syncthreads();
    #pragma unroll
    for (int off = 128; off; off >>= 1) {
        if (threadIdx.x < off) sh[threadIdx.x] += sh[threadIdx.x + off];
        __syncthreads();
    }
    float scale = BETA_F / fmaxf(1.0f, sh[0]);
    if (c4 < C4) {
        *(float4*)(g_cmn + (size_t)r * C_CLS + c4 * 4) =
            make_float4(res.x * scale, res.y * scale,
                        res.z * scale, res.w * scale);
        *(int4*)(g_counts + (size_t)r * C_CLS + c4 * 4) = make_int4(0, 0, 0, 0);
    }
}

// ---------------------------------------------------------------------------
// k3: per-sample gather + product (1 coalesced float2 + 1 L2 gather),
// warp-shuffle reduce -> partials; fenced last block finishes the
// deterministic tree sum, writes -mean, resets g_done for the next replay.
// ---------------------------------------------------------------------------
__global__ __launch_bounds__(256) void k_dot(float* __restrict__ out) {
    int b = blockIdx.x * 256 + threadIdx.x;
    float2 pr = g_pair[b];                       // exactly B_ROWS threads
    float acc = pr.x * g_cmn[__float_as_int(pr.y)];

    #pragma unroll
    for (int off = 16; off; off >>= 1)
        acc += __shfl_xor_sync(0xffffffffu, acc, off);

    __shared__ float shw[8];
    __shared__ bool  is_last;
    int wid = threadIdx.x >> 5;
    if ((threadIdx.x & 31) == 0) shw[wid] = acc;
    __syncthreads();
    if (threadIdx.x == 0) {
        float sB = ((shw[0] + shw[1]) + (shw[2] + shw[3]))
                 + ((shw[4] + shw[5]) + (shw[6] + shw[7]));
        g_partial[blockIdx.x] = sB;
        __threadfence();
        unsigned done = atomicAdd(&g_done, 1u);
        is_last = (done == (unsigned)(DOT_BLOCKS - 1));
    }
    __syncthreads();

    if (is_last) {
        __shared__ float sh[DOT_BLOCKS];
        sh[threadIdx.x] = g_partial[threadIdx.x];
        __syncthreads();
        #pragma unroll
        for (int off = DOT_BLOCKS / 2; off; off >>= 1) {
            if (threadIdx.x < off) sh[threadIdx.x] += sh[threadIdx.x + off];
            __syncthreads();
        }
        if (threadIdx.x == 0) {
            out[0] = -sh[0] / (float)B_ROWS;
            g_done = 0u;                          // ready for next replay
        }
    }
}

extern "C" void kernel_launch(void* const* d_in, const int* in_sizes, int n_in,
                              void* d_out, int out_size) {
    const float* outputs = (const float*)d_in[0];
    const void*  targets = d_in[1];
    const float* cost    = (const float*)d_in[2];
    float* out = (float*)d_out;

    k_rows <<<ROWS_BLOCKS, 256>>>(outputs, targets);  // persistent, 6/SM
    k_scale<<<C_CLS, 256>>>(cost);
    k_dot  <<<DOT_BLOCKS, 256>>>(out);
}